// round 2
// baseline (speedup 1.0000x reference)
#include <cuda_runtime.h>
#include <cuda_bf16.h>

#define NBLOCKS 1184   // 148 SMs * 8 blocks
#define NTHREADS 256

__device__ float2 g_partials[NBLOCKS];
__device__ unsigned int g_ticket = 0;   // self-resetting via atomicInc wrap

__device__ __forceinline__ float2 ldcg_f2(const float2* p) {
    float2 v;
    asm volatile("ld.global.cg.v2.f32 {%0, %1}, [%2];"
                 : "=f"(v.x), "=f"(v.y) : "l"(p));
    return v;
}

__global__ __launch_bounds__(NTHREADS) void loss_kernel(
    const float4* __restrict__ x4,
    const float*  __restrict__ label,
    const float4* __restrict__ pm4,
    const float4* __restrict__ nm4,
    float* __restrict__ out,
    int n4, int hw4)
{
    float s_bce = 0.0f;
    float s_cnt = 0.0f;

    const int stride = gridDim.x * blockDim.x;
    for (int i = blockIdx.x * blockDim.x + threadIdx.x; i < n4; i += stride) {
        float4 xv = x4[i];
        float4 pv = pm4[i];
        float4 nv = nm4[i];
        float y = __ldg(&label[i / hw4]);   // constant within a float4

        {
            float x = xv.x;
            float m = (pv.x > 0.5f && nv.x > 0.5f) ? 1.0f : 0.0f;
            float bce = fmaxf(x, 0.0f) - x * y + log1pf(__expf(-fabsf(x)));
            s_bce += bce * m;  s_cnt += m;
        }
        {
            float x = xv.y;
            float m = (pv.y > 0.5f && nv.y > 0.5f) ? 1.0f : 0.0f;
            float bce = fmaxf(x, 0.0f) - x * y + log1pf(__expf(-fabsf(x)));
            s_bce += bce * m;  s_cnt += m;
        }
        {
            float x = xv.z;
            float m = (pv.z > 0.5f && nv.z > 0.5f) ? 1.0f : 0.0f;
            float bce = fmaxf(x, 0.0f) - x * y + log1pf(__expf(-fabsf(x)));
            s_bce += bce * m;  s_cnt += m;
        }
        {
            float x = xv.w;
            float m = (pv.w > 0.5f && nv.w > 0.5f) ? 1.0f : 0.0f;
            float bce = fmaxf(x, 0.0f) - x * y + log1pf(__expf(-fabsf(x)));
            s_bce += bce * m;  s_cnt += m;
        }
    }

    // Warp reduction
    #pragma unroll
    for (int off = 16; off > 0; off >>= 1) {
        s_bce += __shfl_down_sync(0xFFFFFFFFu, s_bce, off);
        s_cnt += __shfl_down_sync(0xFFFFFFFFu, s_cnt, off);
    }

    // Block reduction
    __shared__ float sh_bce[8];
    __shared__ float sh_cnt[8];
    const int wid = threadIdx.x >> 5;
    const int lid = threadIdx.x & 31;
    if (lid == 0) { sh_bce[wid] = s_bce; sh_cnt[wid] = s_cnt; }
    __syncthreads();

    __shared__ bool is_last;
    if (threadIdx.x < 32) {
        float b = (lid < (NTHREADS >> 5)) ? sh_bce[lid] : 0.0f;
        float c = (lid < (NTHREADS >> 5)) ? sh_cnt[lid] : 0.0f;
        #pragma unroll
        for (int off = 4; off > 0; off >>= 1) {
            b += __shfl_down_sync(0xFFFFFFFFu, b, off);
            c += __shfl_down_sync(0xFFFFFFFFu, c, off);
        }
        if (lid == 0) {
            g_partials[blockIdx.x] = make_float2(b, c);
            __threadfence();
            // atomicInc wraps to 0 after gridDim.x-1 -> self-resetting across graph replays
            unsigned t = atomicInc(&g_ticket, gridDim.x - 1);
            is_last = (t == gridDim.x - 1);
        }
    }
    __syncthreads();

    if (is_last) {
        // Final reduction over all block partials, in double for stability
        double db = 0.0, dc = 0.0;
        for (int i = threadIdx.x; i < (int)gridDim.x; i += blockDim.x) {
            float2 p = ldcg_f2(&g_partials[i]);
            db += (double)p.x;
            dc += (double)p.y;
        }
        #pragma unroll
        for (int off = 16; off > 0; off >>= 1) {
            db += __shfl_down_sync(0xFFFFFFFFu, db, off);
            dc += __shfl_down_sync(0xFFFFFFFFu, dc, off);
        }
        __shared__ double dh_b[8];
        __shared__ double dh_c[8];
        if (lid == 0) { dh_b[wid] = db; dh_c[wid] = dc; }
        __syncthreads();
        if (threadIdx.x < 32) {
            double b2 = (lid < (NTHREADS >> 5)) ? dh_b[lid] : 0.0;
            double c2 = (lid < (NTHREADS >> 5)) ? dh_c[lid] : 0.0;
            #pragma unroll
            for (int off = 4; off > 0; off >>= 1) {
                b2 += __shfl_down_sync(0xFFFFFFFFu, b2, off);
                c2 += __shfl_down_sync(0xFFFFFFFFu, c2, off);
            }
            if (lid == 0) {
                if (c2 < 1.0) c2 = 1.0;
                out[0] = (float)(b2 / c2);
            }
        }
    }
}

extern "C" void kernel_launch(void* const* d_in, const int* in_sizes, int n_in,
                              void* d_out, int out_size) {
    const float* x  = (const float*)d_in[0];  // cancer_logits (B,1,H,W)
    const float* y  = (const float*)d_in[1];  // label (B,)
    const float* pm = (const float*)d_in[2];  // prostate_mask
    const float* nm = (const float*)d_in[3];  // needle_mask

    int n  = in_sizes[0];   // B*H*W
    int nb = in_sizes[1];   // B
    int hw = n / nb;
    int n4 = n / 4;
    int hw4 = hw / 4;

    loss_kernel<<<NBLOCKS, NTHREADS>>>(
        (const float4*)x, y, (const float4*)pm, (const float4*)nm,
        (float*)d_out, n4, hw4);
}

// round 3
// speedup vs baseline: 1.6155x; 1.6155x over previous
#include <cuda_runtime.h>
#include <cuda_bf16.h>

#define NTHREADS 256
#define MAX_BLOCKS 2048

__device__ float2 g_partials[MAX_BLOCKS];
__device__ unsigned int g_ticket = 0;   // self-resetting via atomicInc wrap

__device__ __forceinline__ float2 ldcg_f2(const float2* p) {
    float2 v;
    asm volatile("ld.global.cg.v2.f32 {%0, %1}, [%2];"
                 : "=f"(v.x), "=f"(v.y) : "l"(p));
    return v;
}

__device__ __forceinline__ void accum_elem(float x, float p, float n, float y,
                                           float& s_bce, float& s_cnt) {
    float m   = (fminf(p, n) > 0.5f) ? 1.0f : 0.0f;
    float t   = __expf(-fabsf(x));                       // FMUL + MUFU.EX2
    float sp  = 0.69314718056f * __log2f(1.0f + t);      // FADD + MUFU.LG2 + FMUL
    float bce = fmaxf(x, 0.0f) - x * y + sp;
    s_bce += bce * m;
    s_cnt += m;
}

__global__ __launch_bounds__(NTHREADS) void loss_kernel(
    const float4* __restrict__ x4,
    const float*  __restrict__ label,
    const float4* __restrict__ pm4,
    const float4* __restrict__ nm4,
    float* __restrict__ out,
    int hw4, int nblocks_total)
{
    // Each blockIdx.y handles one batch image: no per-iteration index math.
    const int   b    = blockIdx.y;
    const float y    = __ldg(&label[b]);
    const int   base = b * hw4;

    float s_bce = 0.0f;
    float s_cnt = 0.0f;

    const int stride = gridDim.x * blockDim.x;
    for (int i = blockIdx.x * blockDim.x + threadIdx.x; i < hw4; i += stride) {
        float4 xv = x4[base + i];
        float4 pv = pm4[base + i];
        float4 nv = nm4[base + i];
        accum_elem(xv.x, pv.x, nv.x, y, s_bce, s_cnt);
        accum_elem(xv.y, pv.y, nv.y, y, s_bce, s_cnt);
        accum_elem(xv.z, pv.z, nv.z, y, s_bce, s_cnt);
        accum_elem(xv.w, pv.w, nv.w, y, s_bce, s_cnt);
    }

    // Warp reduction
    #pragma unroll
    for (int off = 16; off > 0; off >>= 1) {
        s_bce += __shfl_down_sync(0xFFFFFFFFu, s_bce, off);
        s_cnt += __shfl_down_sync(0xFFFFFFFFu, s_cnt, off);
    }

    // Block reduction
    __shared__ float sh_bce[8];
    __shared__ float sh_cnt[8];
    const int wid = threadIdx.x >> 5;
    const int lid = threadIdx.x & 31;
    if (lid == 0) { sh_bce[wid] = s_bce; sh_cnt[wid] = s_cnt; }
    __syncthreads();

    __shared__ bool is_last;
    const int blin = blockIdx.y * gridDim.x + blockIdx.x;
    if (threadIdx.x < 32) {
        float bsum = (lid < (NTHREADS >> 5)) ? sh_bce[lid] : 0.0f;
        float csum = (lid < (NTHREADS >> 5)) ? sh_cnt[lid] : 0.0f;
        #pragma unroll
        for (int off = 4; off > 0; off >>= 1) {
            bsum += __shfl_down_sync(0xFFFFFFFFu, bsum, off);
            csum += __shfl_down_sync(0xFFFFFFFFu, csum, off);
        }
        if (lid == 0) {
            g_partials[blin] = make_float2(bsum, csum);
            __threadfence();
            unsigned t = atomicInc(&g_ticket, (unsigned)nblocks_total - 1);
            is_last = (t == (unsigned)nblocks_total - 1);
        }
    }
    __syncthreads();

    if (is_last) {
        double db = 0.0, dc = 0.0;
        for (int i = threadIdx.x; i < nblocks_total; i += blockDim.x) {
            float2 p = ldcg_f2(&g_partials[i]);
            db += (double)p.x;
            dc += (double)p.y;
        }
        #pragma unroll
        for (int off = 16; off > 0; off >>= 1) {
            db += __shfl_down_sync(0xFFFFFFFFu, db, off);
            dc += __shfl_down_sync(0xFFFFFFFFu, dc, off);
        }
        __shared__ double dh_b[8];
        __shared__ double dh_c[8];
        if (lid == 0) { dh_b[wid] = db; dh_c[wid] = dc; }
        __syncthreads();
        if (threadIdx.x < 32) {
            double b2 = (lid < (NTHREADS >> 5)) ? dh_b[lid] : 0.0;
            double c2 = (lid < (NTHREADS >> 5)) ? dh_c[lid] : 0.0;
            #pragma unroll
            for (int off = 4; off > 0; off >>= 1) {
                b2 += __shfl_down_sync(0xFFFFFFFFu, b2, off);
                c2 += __shfl_down_sync(0xFFFFFFFFu, c2, off);
            }
            if (lid == 0) {
                if (c2 < 1.0) c2 = 1.0;
                out[0] = (float)(b2 / c2);
            }
        }
    }
}

extern "C" void kernel_launch(void* const* d_in, const int* in_sizes, int n_in,
                              void* d_out, int out_size) {
    const float* x  = (const float*)d_in[0];  // cancer_logits (B,1,H,W)
    const float* y  = (const float*)d_in[1];  // label (B,)
    const float* pm = (const float*)d_in[2];  // prostate_mask
    const float* nm = (const float*)d_in[3];  // needle_mask

    int n   = in_sizes[0];   // B*H*W
    int nb  = in_sizes[1];   // B
    int hw4 = (n / nb) / 4;  // float4s per image

    // ~8 blocks/SM total: blocks_per_batch * nb ≈ 1184
    int bpb = (8 * 148 + nb - 1) / nb;            // 37 for B=32
    if (bpb * nb > MAX_BLOCKS) bpb = MAX_BLOCKS / nb;
    int nblocks_total = bpb * nb;

    dim3 grid(bpb, nb, 1);
    loss_kernel<<<grid, NTHREADS>>>(
        (const float4*)x, y, (const float4*)pm, (const float4*)nm,
        (float*)d_out, hw4, nblocks_total);
}